// round 2
// baseline (speedup 1.0000x reference)
#include <cuda_runtime.h>
#include <math.h>

// Problem constants
#define B_   8
#define C_   64
#define T_   256
#define F_   256
#define H_   128
#define KT_  192   // C_ + H_
#define NSEQ 2048  // sequences per GRU (B*F == B*T)
#define VS_  196   // v_s row stride in floats (192 data + pad, multiple of 4)

// ---------------- scratch (static device globals; no allocation) ----------------
__device__ float g_xt[(size_t)B_ * T_ * F_ * C_];        // x transposed to [B,T,F,C]  (134 MB)
__device__ float g_wpack[2 * KT_ * 3 * H_];              // [gru][k][gate(r,z,n)][j]
__device__ float g_bias[2 * 4 * H_];                     // [gru][{br,bz,bni,bnh}][j]
__device__ float g_hout[2 * NSEQ * H_];                  // final hidden states

// ---------------- weight packing ----------------
// g_wpack[((g*KT_ + k)*3 + gate)*H_ + j] =
//   k <  64 : Wih[gate*H_+j][k]
//   k >= 64 : Whh[gate*H_+j][k-64]
__global__ void prep_kernel(const float* __restrict__ Wih_t, const float* __restrict__ Whh_t,
                            const float* __restrict__ bih_t, const float* __restrict__ bhh_t,
                            const float* __restrict__ Wih_f, const float* __restrict__ Whh_f,
                            const float* __restrict__ bih_f, const float* __restrict__ bhh_f) {
    int idx = blockIdx.x * blockDim.x + threadIdx.x;
    const int total = 2 * KT_ * 3 * H_;
    if (idx < total) {
        int j    = idx & (H_ - 1);
        int gate = (idx >> 7) % 3;
        int k    = (idx / (3 * H_)) % KT_;
        int g    = idx / (KT_ * 3 * H_);
        const float* Wih = g ? Wih_f : Wih_t;
        const float* Whh = g ? Whh_f : Whh_t;
        int row = gate * H_ + j;
        float v = (k < C_) ? Wih[row * C_ + k] : Whh[row * H_ + (k - C_)];
        g_wpack[idx] = v;
    }
    if (idx < 2 * H_) {
        int g = idx >> 7;
        int j = idx & (H_ - 1);
        const float* bih = g ? bih_f : bih_t;
        const float* bhh = g ? bhh_f : bhh_t;
        float* dst = &g_bias[g * 4 * H_];
        dst[0 * H_ + j] = bih[j]          + bhh[j];           // r
        dst[1 * H_ + j] = bih[H_ + j]     + bhh[H_ + j];      // z
        dst[2 * H_ + j] = bih[2 * H_ + j];                    // n (input part)
        dst[3 * H_ + j] = bhh[2 * H_ + j];                    // n (hidden part)
    }
}

// ---------------- x transpose: [B,C,T,F] -> [B,T,F,C] ----------------
__global__ void transpose_kernel(const float* __restrict__ x) {
    __shared__ float tile[64][65];
    int bx = blockIdx.x;
    int fc = bx & 3;           // which 64-wide f chunk
    int t  = (bx >> 2) & 255;
    int b  = bx >> 10;
    int f0 = fc << 6;
    int tid = threadIdx.x;
#pragma unroll
    for (int i = 0; i < 16; i++) {
        int idx = tid + i * 256;
        int c = idx >> 6, ff = idx & 63;
        tile[c][ff] = x[(((size_t)(b * 64 + c) * 256 + t) << 8) + f0 + ff];
    }
    __syncthreads();
#pragma unroll
    for (int i = 0; i < 16; i++) {
        int idx = tid + i * 256;
        int ff = idx >> 6, c = idx & 63;
        g_xt[((size_t)((b * 256 + t) * 256 + f0 + ff) << 6) + c] = tile[c][ff];
    }
}

// ---------------- fused dual-GRU recurrent kernel ----------------
// grid: 256 CTAs. CTA = (gru g, 16 sequences). 256 threads = (j in 0..127) x (grp in 0..1),
// each thread accumulates gates for 8 sequences at hidden column j.
__device__ __forceinline__ float sigmoidf_(float x) {
    return 1.0f / (1.0f + __expf(-x));
}

__global__ void __launch_bounds__(256, 2) gru_kernel() {
    __shared__ float v_s[16 * VS_];   // per seq: [0..63] x_t, [64..191] h
    const int g   = blockIdx.x >> 7;
    const int seg = blockIdx.x & 127;
    const int n0  = seg * 16;
    const int tid = threadIdx.x;
    const int j   = tid & 127;
    const int grp = tid >> 7;

    const float* wbase = g_wpack + (size_t)g * (KT_ * 3 * H_) + j;
    const float* bb    = g_bias + g * (4 * H_) + j;
    const float  br = bb[0], bz = bb[H_], bni = bb[2 * H_], bnh = bb[3 * H_];

    for (int e = tid; e < 16 * VS_; e += 256) v_s[e] = 0.0f;   // h0 = 0
    __syncthreads();

    // per-thread x-load slot: one float4 per step
    const int lseq = tid >> 4;       // 0..15
    const int lc4  = tid & 15;       // 0..15 (float4 within 64 floats)
    size_t xoff;
    int    xstride;
    if (g == 0) {   // time GRU: seq n = b*F + f, step = t
        int b  = n0 >> 8;
        int f0 = n0 & 255;
        xoff    = (size_t)b * T_ * F_ * C_ + (size_t)(f0 + lseq) * C_ + lc4 * 4;
        xstride = F_ * C_;           // advance t
    } else {        // freq GRU: seq n = b*T + t, step = f
        xoff    = (size_t)(n0 + lseq) * F_ * C_ + lc4 * 4;
        xstride = C_;                // advance f
    }
    const float* xptr = g_xt + xoff;
    float* vdst = &v_s[lseq * VS_ + lc4 * 4];

    const float* vrow = &v_s[grp * 8 * VS_];
    float hnew[8];
#pragma unroll
    for (int n = 0; n < 8; n++) hnew[n] = 0.0f;

    for (int s = 0; s < T_; s++) {
        // stage x_t for this step
        *(float4*)vdst = *(const float4*)xptr;
        xptr += xstride;
        __syncthreads();

        float ar[8], az[8], ni[8], nh[8];
#pragma unroll
        for (int n = 0; n < 8; n++) { ar[n] = br; az[n] = bz; ni[n] = bni; nh[n] = bnh; }

        // phase 1: input part (k = 0..63) -> ar, az, ni
#pragma unroll 2
        for (int k4 = 0; k4 < 64; k4 += 4) {
            float4 vv[8];
#pragma unroll
            for (int n = 0; n < 8; n++) vv[n] = *(const float4*)&vrow[n * VS_ + k4];
#pragma unroll
            for (int kk = 0; kk < 4; kk++) {
                const float* w = wbase + (size_t)(k4 + kk) * (3 * H_);
                float wr = w[0], wz = w[H_], wn = w[2 * H_];
#pragma unroll
                for (int n = 0; n < 8; n++) {
                    float v = ((const float*)&vv[n])[kk];
                    ar[n] = fmaf(v, wr, ar[n]);
                    az[n] = fmaf(v, wz, az[n]);
                    ni[n] = fmaf(v, wn, ni[n]);
                }
            }
        }
        // phase 2: hidden part (k = 64..191) -> ar, az, nh
#pragma unroll 2
        for (int k4 = 64; k4 < 192; k4 += 4) {
            float4 vv[8];
#pragma unroll
            for (int n = 0; n < 8; n++) vv[n] = *(const float4*)&vrow[n * VS_ + k4];
#pragma unroll
            for (int kk = 0; kk < 4; kk++) {
                const float* w = wbase + (size_t)(k4 + kk) * (3 * H_);
                float wr = w[0], wz = w[H_], wn = w[2 * H_];
#pragma unroll
                for (int n = 0; n < 8; n++) {
                    float v = ((const float*)&vv[n])[kk];
                    ar[n] = fmaf(v, wr, ar[n]);
                    az[n] = fmaf(v, wz, az[n]);
                    nh[n] = fmaf(v, wn, nh[n]);
                }
            }
        }

        // gate math + h update
#pragma unroll
        for (int n = 0; n < 8; n++) {
            float h_old = v_s[(grp * 8 + n) * VS_ + 64 + j];
            float r  = sigmoidf_(ar[n]);
            float z  = sigmoidf_(az[n]);
            float nn = tanhf(fmaf(r, nh[n], ni[n]));
            hnew[n] = (1.0f - z) * nn + z * h_old;
        }
        __syncthreads();   // all reads of v_s done
#pragma unroll
        for (int n = 0; n < 8; n++) v_s[(grp * 8 + n) * VS_ + 64 + j] = hnew[n];
        __syncthreads();
    }

#pragma unroll
    for (int n = 0; n < 8; n++)
        g_hout[((size_t)g * NSEQ + n0 + grp * 8 + n) * H_ + j] = hnew[n];
}

// ---------------- output projection + broadcast ----------------
// out[b,c,t,f] = bp[c] + sum_h Wp[c,h] * (h_time[b*F+t][h] + h_freq[b*T+t][h])
__global__ void out_kernel(const float* __restrict__ Wp, const float* __restrict__ bp,
                           float* __restrict__ out) {
    __shared__ float s_vec[H_];
    __shared__ float part_s[4][64];
    __shared__ float s_out[64];
    const int bt = blockIdx.x;
    const int b  = bt >> 8;
    const int t  = bt & 255;
    const int tid = threadIdx.x;
    const int nidx = b * 256 + t;

    if (tid < H_)
        s_vec[tid] = g_hout[(size_t)nidx * H_ + tid] +
                     g_hout[((size_t)NSEQ + nidx) * H_ + tid];
    __syncthreads();

    const int c = tid & 63, p = tid >> 6;
    float sum = 0.0f;
#pragma unroll
    for (int h = 0; h < 32; h++)
        sum = fmaf(Wp[c * H_ + p * 32 + h], s_vec[p * 32 + h], sum);
    part_s[p][c] = sum;
    __syncthreads();
    if (tid < 64)
        s_out[tid] = bp[tid] + part_s[0][tid] + part_s[1][tid] + part_s[2][tid] + part_s[3][tid];
    __syncthreads();

    float4* o4 = (float4*)out;
    const size_t base4 = ((size_t)b * 64) * 16384 + (size_t)t * 64;
    for (int e = tid; e < 4096; e += 256) {
        int c2 = e >> 6, f4 = e & 63;
        float v = s_out[c2];
        o4[base4 + (size_t)c2 * 16384 + f4] = make_float4(v, v, v, v);
    }
}

// ---------------- launcher ----------------
extern "C" void kernel_launch(void* const* d_in, const int* in_sizes, int n_in,
                              void* d_out, int out_size) {
    const float* x     = (const float*)d_in[0];
    const float* Wih_t = (const float*)d_in[1];
    const float* Whh_t = (const float*)d_in[2];
    const float* bih_t = (const float*)d_in[3];
    const float* bhh_t = (const float*)d_in[4];
    const float* Wih_f = (const float*)d_in[5];
    const float* Whh_f = (const float*)d_in[6];
    const float* bih_f = (const float*)d_in[7];
    const float* bhh_f = (const float*)d_in[8];
    const float* Wp    = (const float*)d_in[9];
    const float* bp    = (const float*)d_in[10];
    float* out = (float*)d_out;

    prep_kernel<<<(2 * KT_ * 3 * H_ + 255) / 256, 256>>>(Wih_t, Whh_t, bih_t, bhh_t,
                                                         Wih_f, Whh_f, bih_f, bhh_f);
    transpose_kernel<<<B_ * T_ * (F_ / 64), 256>>>(x);
    gru_kernel<<<256, 256>>>();
    out_kernel<<<B_ * T_, 256>>>(Wp, bp, out);
}

// round 3
// speedup vs baseline: 1.3258x; 1.3258x over previous
#include <cuda_runtime.h>
#include <math.h>

// Problem constants
#define B_   8
#define C_   64
#define T_   256
#define F_   256
#define H_   128
#define NSEQ 2048  // sequences per GRU (B*F == B*T)

// ---------------- scratch (static device globals; no allocation) ----------------
// pair-interleaved transposed inputs:
//   g_xtm[((b*256 + t)*128 + fp)*128 + c*2 + e]  = x[b, c, t, 2*fp+e]   (time GRU)
//   g_xf [((b*256 + f)*128 + tp)*128 + c*2 + e]  = x[b, c, 2*tp+e, f]   (freq GRU)
__device__ float g_xtm[(size_t)B_ * T_ * F_ * C_];
__device__ float g_xf [(size_t)B_ * T_ * F_ * C_];
// weights packed for LDG.128 per thread-j:
//   g_w4[(((g*48 + k4)*3 + gate)*128 + j)*4 + kk] = W[gate*128+j][k4*4+kk]
//   (k < 64 from Wih, k >= 64 from Whh)
__device__ float g_w4[2 * 48 * 3 * 512];
__device__ float g_bias[2 * 4 * H_];       // [gru][{br,bz,bni,bnh}][j]
__device__ float g_hout[2 * NSEQ * H_];    // final hidden states

// ---------------- f32x2 helpers ----------------
__device__ __forceinline__ unsigned long long pack2(float a, float b) {
    unsigned long long r;
    asm("mov.b64 %0, {%1, %2};" : "=l"(r) : "f"(a), "f"(b));
    return r;
}
__device__ __forceinline__ float2 unpack2(unsigned long long v) {
    float2 f;
    asm("mov.b64 {%0, %1}, %2;" : "=f"(f.x), "=f"(f.y) : "l"(v));
    return f;
}
__device__ __forceinline__ void fma2(unsigned long long& d, unsigned long long a,
                                     unsigned long long b) {
    asm("fma.rn.f32x2 %0, %1, %2, %0;" : "+l"(d) : "l"(a), "l"(b));
}
__device__ __forceinline__ float tanha(float x) {
    float y;
    asm("tanh.approx.f32 %0, %1;" : "=f"(y) : "f"(x));
    return y;
}

// ---------------- weight packing ----------------
__global__ void prep_kernel(const float* __restrict__ Wih_t, const float* __restrict__ Whh_t,
                            const float* __restrict__ bih_t, const float* __restrict__ bhh_t,
                            const float* __restrict__ Wih_f, const float* __restrict__ Whh_f,
                            const float* __restrict__ bih_f, const float* __restrict__ bhh_f) {
    int idx = blockIdx.x * blockDim.x + threadIdx.x;
    const int total = 2 * 48 * 3 * 512;   // 147456
    if (idx < total) {
        int kk   = idx & 3;
        int j    = (idx >> 2) & 127;
        int gate = (idx >> 9) % 3;
        int k4   = (idx / 1536) % 48;
        int g    = idx / (1536 * 48);
        int k    = k4 * 4 + kk;
        const float* Wih = g ? Wih_f : Wih_t;
        const float* Whh = g ? Whh_f : Whh_t;
        int row = gate * H_ + j;
        float v = (k < C_) ? Wih[row * C_ + k] : Whh[row * H_ + (k - C_)];
        g_w4[idx] = v;
    }
    if (idx < 2 * H_) {
        int g = idx >> 7;
        int j = idx & 127;
        const float* bih = g ? bih_f : bih_t;
        const float* bhh = g ? bhh_f : bhh_t;
        float* dst = &g_bias[g * 4 * H_];
        dst[0 * H_ + j] = bih[j]          + bhh[j];           // r
        dst[1 * H_ + j] = bih[H_ + j]     + bhh[H_ + j];      // z
        dst[2 * H_ + j] = bih[2 * H_ + j];                    // n (input part)
        dst[3 * H_ + j] = bhh[2 * H_ + j];                    // n (hidden part)
    }
}

// ---------------- x transpose -> pair-interleaved layouts ----------------
// CTA handles (b, t-pair t0..t0+1, f-chunk of 64).
__global__ void transpose_kernel(const float* __restrict__ x) {
    __shared__ float tile[2][64][66];
    int bx = blockIdx.x;
    int fc = bx & 3;
    int tp = (bx >> 2) & 127;
    int b  = bx >> 9;
    int f0 = fc << 6;
    int t0 = tp << 1;
    int tid = threadIdx.x;

    // read x[b, c, t0+tt, f0..f0+63]
#pragma unroll
    for (int i = 0; i < 32; i++) {
        int idx = tid + i * 256;
        int f  = idx & 63;
        int c  = (idx >> 6) & 63;
        int tt = idx >> 12;
        tile[tt][c][f] = x[(((size_t)(b * 64 + c) * 256 + t0 + tt) << 8) + f0 + f];
    }
    __syncthreads();

    // xt_time: per t, contiguous 4096 floats at ((b*256+t)*128 + f0/2)*128
#pragma unroll
    for (int tt = 0; tt < 2; tt++) {
        float* dst = g_xtm + (((size_t)(b * 256 + t0 + tt) * 128) + (f0 >> 1)) * 128;
#pragma unroll
        for (int i = 0; i < 16; i++) {
            int idx = tid + i * 256;
            int e   = idx & 1;
            int c   = (idx >> 1) & 63;
            int fpl = idx >> 7;
            dst[idx] = tile[tt][c][2 * fpl + e];
        }
    }
    // xt_freq: per f, contiguous 128 floats at ((b*256+f)*128 + t0/2)*128
#pragma unroll
    for (int i = 0; i < 32; i++) {
        int idx = tid + i * 256;
        int e  = idx & 1;
        int c  = (idx >> 1) & 63;
        int fl = idx >> 7;
        g_xf[(((size_t)(b * 256 + f0 + fl) * 128) + tp) * 128 + c * 2 + e] = tile[e][c][fl];
    }
}

// ---------------- fused dual-GRU recurrent kernel ----------------
// 256 CTAs x 128 threads. CTA = (gru g, 16 sequences = 8 adjacent pairs).
// Thread j owns hidden column j for all 8 pairs; activations as f32x2 pairs.
__global__ void __launch_bounds__(128, 2) gru_kernel() {
    __shared__ __align__(16) float sx[2][1024];   // [buf][pair(8)][c(64)][e(2)]
    __shared__ __align__(16) float sh[2][2048];   // [buf][pair(8)][j(128)][e(2)]

    const int g   = blockIdx.x >> 7;
    const int seg = blockIdx.x & 127;
    const int n0  = seg * 16;          // first sequence
    const int b   = n0 >> 8;
    const int pp0 = (n0 & 255) >> 1;   // first pair index within b
    const int j   = threadIdx.x;       // 0..127

    const float* xsrc = (g == 0 ? g_xtm : g_xf) +
                        ((size_t)b * 256 * 128 + pp0) * (size_t)128;
    const float* wb = g_w4 + (size_t)g * (48 * 3 * 512) + j * 4;
    const float* bb = g_bias + g * (4 * H_) + j;
    const unsigned long long brp  = pack2(bb[0], bb[0]);
    const unsigned long long bzp  = pack2(bb[H_], bb[H_]);
    const unsigned long long bnip = pack2(bb[2 * H_], bb[2 * H_]);
    const unsigned long long bnhp = pack2(bb[3 * H_], bb[3 * H_]);

    // h0 = 0
#pragma unroll
    for (int i = 0; i < 16; i++) sh[0][j + i * 128] = 0.0f;
    // stage x for step 0
    {
        const float4* xp = (const float4*)xsrc;
        ((float4*)sx[0])[j * 2]     = xp[j * 2];
        ((float4*)sx[0])[j * 2 + 1] = xp[j * 2 + 1];
    }
    __syncthreads();

    for (int s = 0; s < T_; s++) {
        const int cur = s & 1, nxt = cur ^ 1;

        // prefetch next step's x
        float4 px0, px1;
        if (s < T_ - 1) {
            const float4* xp = (const float4*)(xsrc + (size_t)(s + 1) * 16384);
            px0 = xp[j * 2];
            px1 = xp[j * 2 + 1];
        }

        unsigned long long ar[8], az[8], ani[8], anh[8];
#pragma unroll
        for (int p = 0; p < 8; p++) { ar[p] = brp; az[p] = bzp; ani[p] = bnip; anh[p] = bnhp; }

        // phase 1: input part (k = 0..63) from sx[cur]
#pragma unroll 4
        for (int q = 0; q < 16; q++) {
            const float* w = wb + q * 1536;
            float4 wr4 = *(const float4*)(w);
            float4 wz4 = *(const float4*)(w + 512);
            float4 wn4 = *(const float4*)(w + 1024);
            unsigned long long wr[4], wz[4], wn[4];
            wr[0] = pack2(wr4.x, wr4.x); wr[1] = pack2(wr4.y, wr4.y);
            wr[2] = pack2(wr4.z, wr4.z); wr[3] = pack2(wr4.w, wr4.w);
            wz[0] = pack2(wz4.x, wz4.x); wz[1] = pack2(wz4.y, wz4.y);
            wz[2] = pack2(wz4.z, wz4.z); wz[3] = pack2(wz4.w, wz4.w);
            wn[0] = pack2(wn4.x, wn4.x); wn[1] = pack2(wn4.y, wn4.y);
            wn[2] = pack2(wn4.z, wn4.z); wn[3] = pack2(wn4.w, wn4.w);
#pragma unroll
            for (int p = 0; p < 8; p++) {
                const ulonglong2* v = (const ulonglong2*)&sx[cur][p * 128 + q * 8];
                ulonglong2 v01 = v[0];
                ulonglong2 v23 = v[1];
                fma2(ar[p],  v01.x, wr[0]); fma2(az[p],  v01.x, wz[0]); fma2(ani[p], v01.x, wn[0]);
                fma2(ar[p],  v01.y, wr[1]); fma2(az[p],  v01.y, wz[1]); fma2(ani[p], v01.y, wn[1]);
                fma2(ar[p],  v23.x, wr[2]); fma2(az[p],  v23.x, wz[2]); fma2(ani[p], v23.x, wn[2]);
                fma2(ar[p],  v23.y, wr[3]); fma2(az[p],  v23.y, wz[3]); fma2(ani[p], v23.y, wn[3]);
            }
        }
        // phase 2: hidden part (k = 64..191) from sh[cur]
#pragma unroll 4
        for (int q = 0; q < 32; q++) {
            const float* w = wb + (16 + q) * 1536;
            float4 wr4 = *(const float4*)(w);
            float4 wz4 = *(const float4*)(w + 512);
            float4 wn4 = *(const float4*)(w + 1024);
            unsigned long long wr[4], wz[4], wn[4];
            wr[0] = pack2(wr4.x, wr4.x); wr[1] = pack2(wr4.y, wr4.y);
            wr[2] = pack2(wr4.z, wr4.z); wr[3] = pack2(wr4.w, wr4.w);
            wz[0] = pack2(wz4.x, wz4.x); wz[1] = pack2(wz4.y, wz4.y);
            wz[2] = pack2(wz4.z, wz4.z); wz[3] = pack2(wz4.w, wz4.w);
            wn[0] = pack2(wn4.x, wn4.x); wn[1] = pack2(wn4.y, wn4.y);
            wn[2] = pack2(wn4.z, wn4.z); wn[3] = pack2(wn4.w, wn4.w);
#pragma unroll
            for (int p = 0; p < 8; p++) {
                const ulonglong2* v = (const ulonglong2*)&sh[cur][p * 256 + q * 8];
                ulonglong2 v01 = v[0];
                ulonglong2 v23 = v[1];
                fma2(ar[p],  v01.x, wr[0]); fma2(az[p],  v01.x, wz[0]); fma2(anh[p], v01.x, wn[0]);
                fma2(ar[p],  v01.y, wr[1]); fma2(az[p],  v01.y, wz[1]); fma2(anh[p], v01.y, wn[1]);
                fma2(ar[p],  v23.x, wr[2]); fma2(az[p],  v23.x, wz[2]); fma2(anh[p], v23.x, wn[2]);
                fma2(ar[p],  v23.y, wr[3]); fma2(az[p],  v23.y, wz[3]); fma2(anh[p], v23.y, wn[3]);
            }
        }

        // gate math + h update (per pair, 2 lanes)
#pragma unroll
        for (int p = 0; p < 8; p++) {
            float2 vr = unpack2(ar[p]);
            float2 vz = unpack2(az[p]);
            float2 vi = unpack2(ani[p]);
            float2 vh = unpack2(anh[p]);
            float2 ho = unpack2(*(const unsigned long long*)&sh[cur][p * 256 + j * 2]);
            float rx = 0.5f * tanha(0.5f * vr.x) + 0.5f;
            float ry = 0.5f * tanha(0.5f * vr.y) + 0.5f;
            float zx = 0.5f * tanha(0.5f * vz.x) + 0.5f;
            float zy = 0.5f * tanha(0.5f * vz.y) + 0.5f;
            float nx = tanha(fmaf(rx, vh.x, vi.x));
            float ny = tanha(fmaf(ry, vh.y, vi.y));
            float hx = nx + zx * (ho.x - nx);
            float hy = ny + zy * (ho.y - ny);
            *(unsigned long long*)&sh[nxt][p * 256 + j * 2] = pack2(hx, hy);
        }
        // stage x for next step
        if (s < T_ - 1) {
            ((float4*)sx[nxt])[j * 2]     = px0;
            ((float4*)sx[nxt])[j * 2 + 1] = px1;
        }
        __syncthreads();
    }

    // final h lives in sh[0] (last write at s=255: nxt = 0)
#pragma unroll
    for (int p = 0; p < 8; p++) {
        float2 h2 = unpack2(*(const unsigned long long*)&sh[0][p * 256 + j * 2]);
        g_hout[((size_t)g * NSEQ + n0 + 2 * p) * H_ + j]     = h2.x;
        g_hout[((size_t)g * NSEQ + n0 + 2 * p + 1) * H_ + j] = h2.y;
    }
}

// ---------------- output projection + broadcast ----------------
// out[b,c,t,f] = bp[c] + sum_h Wp[c,h] * (h_time[b*F+t][h] + h_freq[b*T+t][h])
__global__ void out_kernel(const float* __restrict__ Wp, const float* __restrict__ bp,
                           float* __restrict__ out) {
    __shared__ float s_vec[H_];
    __shared__ float part_s[4][64];
    __shared__ float s_out[64];
    const int bt = blockIdx.x;
    const int b  = bt >> 8;
    const int t  = bt & 255;
    const int tid = threadIdx.x;
    const int nidx = b * 256 + t;

    if (tid < H_)
        s_vec[tid] = g_hout[(size_t)nidx * H_ + tid] +
                     g_hout[((size_t)NSEQ + nidx) * H_ + tid];
    __syncthreads();

    const int c = tid & 63, p = tid >> 6;
    float sum = 0.0f;
#pragma unroll
    for (int h = 0; h < 32; h++)
        sum = fmaf(Wp[c * H_ + p * 32 + h], s_vec[p * 32 + h], sum);
    part_s[p][c] = sum;
    __syncthreads();
    if (tid < 64)
        s_out[tid] = bp[tid] + part_s[0][tid] + part_s[1][tid] + part_s[2][tid] + part_s[3][tid];
    __syncthreads();

    float4* o4 = (float4*)out;
    const size_t base4 = ((size_t)b * 64) * 16384 + (size_t)t * 64;
    for (int e = tid; e < 4096; e += 256) {
        int c2 = e >> 6, f4 = e & 63;
        float v = s_out[c2];
        o4[base4 + (size_t)c2 * 16384 + f4] = make_float4(v, v, v, v);
    }
}

// ---------------- launcher ----------------
extern "C" void kernel_launch(void* const* d_in, const int* in_sizes, int n_in,
                              void* d_out, int out_size) {
    const float* x     = (const float*)d_in[0];
    const float* Wih_t = (const float*)d_in[1];
    const float* Whh_t = (const float*)d_in[2];
    const float* bih_t = (const float*)d_in[3];
    const float* bhh_t = (const float*)d_in[4];
    const float* Wih_f = (const float*)d_in[5];
    const float* Whh_f = (const float*)d_in[6];
    const float* bih_f = (const float*)d_in[7];
    const float* bhh_f = (const float*)d_in[8];
    const float* Wp    = (const float*)d_in[9];
    const float* bp    = (const float*)d_in[10];
    float* out = (float*)d_out;

    prep_kernel<<<(2 * 48 * 3 * 512 + 255) / 256, 256>>>(Wih_t, Whh_t, bih_t, bhh_t,
                                                         Wih_f, Whh_f, bih_f, bhh_f);
    transpose_kernel<<<B_ * (T_ / 2) * (F_ / 64), 256>>>(x);
    gru_kernel<<<256, 128>>>();
    out_kernel<<<B_ * T_, 256>>>(Wp, bp, out);
}

// round 5
// speedup vs baseline: 3.6573x; 2.7585x over previous
#include <cuda_runtime.h>
#include <cuda_bf16.h>
#include <stdint.h>

#define NSEQ 2048

// ---------------- device scratch ----------------
// per (g, sb, step) 8KB block: [plane(hi/lo)][n 32][k 64] bf16 (x part, k=0..63)
__device__ unsigned char g_xn[(size_t)2 * 64 * 256 * 8192];
__device__ __nv_bfloat16 g_whi[2 * 384 * 192];   // permuted rows: rp = w*48 + sec*16 + jj
__device__ __nv_bfloat16 g_wlo[2 * 384 * 192];
__device__ float g_bias[2 * 4 * 128];            // [g][{br,bz,bni,bnh}][j]
__device__ float g_hout[2 * NSEQ * 128];

// ---------------- helpers ----------------
__device__ __forceinline__ uint32_t smem_u32(const void* p) {
    uint32_t a;
    asm("{ .reg .u64 t; cvta.to.shared.u64 t, %1; cvt.u32.u64 %0, t; }" : "=r"(a) : "l"(p));
    return a;
}
__device__ __forceinline__ float tanha(float x) {
    float y; asm("tanh.approx.f32 %0, %1;" : "=f"(y) : "f"(x)); return y;
}
__device__ __forceinline__ float siga(float x) { return 0.5f * tanha(0.5f * x) + 0.5f; }
__device__ __forceinline__ uint32_t pack_bf2(__nv_bfloat16 a, __nv_bfloat16 b) {
    return (uint32_t)__bfloat16_as_ushort(a) | ((uint32_t)__bfloat16_as_ushort(b) << 16);
}
__device__ __forceinline__ void ldsm4(uint32_t* r, uint32_t addr) {
    asm volatile("ldmatrix.sync.aligned.m8n8.x4.shared.b16 {%0,%1,%2,%3}, [%4];"
        : "=r"(r[0]), "=r"(r[1]), "=r"(r[2]), "=r"(r[3]) : "r"(addr));
}
__device__ __forceinline__ void ldsm2(uint32_t* r, uint32_t addr) {
    asm volatile("ldmatrix.sync.aligned.m8n8.x2.shared.b16 {%0,%1}, [%2];"
        : "=r"(r[0]), "=r"(r[1]) : "r"(addr));
}
__device__ __forceinline__ void mma16816(float* c, const uint32_t* a, const uint32_t* b) {
    asm volatile("mma.sync.aligned.m16n8k16.row.col.f32.bf16.bf16.f32 "
        "{%0,%1,%2,%3}, {%4,%5,%6,%7}, {%8,%9}, {%0,%1,%2,%3};"
        : "+f"(c[0]), "+f"(c[1]), "+f"(c[2]), "+f"(c[3])
        : "r"(a[0]), "r"(a[1]), "r"(a[2]), "r"(a[3]), "r"(b[0]), "r"(b[1]));
}

// ---------------- prep: permuted hi/lo weight planes + fused biases ----------------
__global__ void prep_kernel(const float* __restrict__ Wih_t, const float* __restrict__ Whh_t,
                            const float* __restrict__ bih_t, const float* __restrict__ bhh_t,
                            const float* __restrict__ Wih_f, const float* __restrict__ Whh_f,
                            const float* __restrict__ bih_f, const float* __restrict__ bhh_f) {
    int idx = blockIdx.x * blockDim.x + threadIdx.x;
    const int NW = 2 * 384 * 192;
    if (idx < NW) {
        int k  = idx % 192;
        int rp = (idx / 192) % 384;
        int g  = idx / (384 * 192);
        int w = rp / 48, rem = rp % 48, sec = rem / 16, jj = rem % 16;
        int orig = sec * 128 + w * 16 + jj;     // gate-major original row
        const float* Wih = g ? Wih_f : Wih_t;
        const float* Whh = g ? Whh_f : Whh_t;
        float v = (k < 64) ? Wih[orig * 64 + k] : Whh[orig * 128 + (k - 64)];
        __nv_bfloat16 hi = __float2bfloat16(v);
        g_whi[idx] = hi;
        g_wlo[idx] = __float2bfloat16(v - __bfloat162float(hi));
    } else if (idx < NW + 256) {
        int t = idx - NW;
        int g = t >> 7, j = t & 127;
        const float* bih = g ? bih_f : bih_t;
        const float* bhh = g ? bhh_f : bhh_t;
        float* dst = &g_bias[g * 512];
        dst[0 * 128 + j] = bih[j] + bhh[j];
        dst[1 * 128 + j] = bih[128 + j] + bhh[128 + j];
        dst[2 * 128 + j] = bih[256 + j];
        dst[3 * 128 + j] = bhh[256 + j];
    }
}

// ---------------- transpose: build n-major bf16 hi/lo x images ----------------
// CTA = (b, t-block of 8, f-block of 32); 256 threads; slab[64][257] floats
__global__ void transpose_kernel(const float* __restrict__ x) {
    extern __shared__ float slab[];
    const int bx = blockIdx.x;
    const int fb = bx & 7;
    const int tb = (bx >> 3) & 31;
    const int b  = bx >> 8;
    const int f0 = fb * 32, t0 = tb * 8;
    const int tid = threadIdx.x;
#pragma unroll
    for (int i = 0; i < 16; i++) {
        int idx = tid + i * 256;
        int f4 = idx & 7, tt = (idx >> 3) & 7, c = idx >> 6;
        float4 v = ((const float4*)x)[(((size_t)(b * 64 + c) * 256 + t0 + tt) << 6) + (f0 >> 2) + f4];
        float* d = &slab[c * 257 + tt * 32 + f4 * 4];
        d[0] = v.x; d[1] = v.y; d[2] = v.z; d[3] = v.w;
    }
    __syncthreads();
    const int tt = tid >> 5, ff = tid & 31;
    const int t = t0 + tt, f = f0 + ff;
    uint32_t hiw[32], low[32];
#pragma unroll
    for (int q = 0; q < 32; q++) {
        float v0 = slab[(2 * q) * 257 + tt * 32 + ff];
        float v1 = slab[(2 * q + 1) * 257 + tt * 32 + ff];
        __nv_bfloat16 h0 = __float2bfloat16(v0), h1 = __float2bfloat16(v1);
        __nv_bfloat16 l0 = __float2bfloat16(v0 - __bfloat162float(h0));
        __nv_bfloat16 l1 = __float2bfloat16(v1 - __bfloat162float(h1));
        hiw[q] = pack_bf2(h0, h1);
        low[q] = pack_bf2(l0, l1);
    }
    // g0: sb = b*8+fb, step = t, n = ff
    {
        unsigned char* dst = g_xn + ((size_t)(0 * 64 + b * 8 + fb) * 256 + t) * 8192 + ff * 128;
#pragma unroll
        for (int q = 0; q < 8; q++) ((uint4*)dst)[q]          = *(uint4*)&hiw[q * 4];
#pragma unroll
        for (int q = 0; q < 8; q++) ((uint4*)(dst + 4096))[q] = *(uint4*)&low[q * 4];
    }
    // g1: sb = b*8 + (t>>5), step = f, n = t&31
    {
        unsigned char* dst = g_xn + ((size_t)(1 * 64 + b * 8 + (t >> 5)) * 256 + f) * 8192 + (t & 31) * 128;
#pragma unroll
        for (int q = 0; q < 8; q++) ((uint4*)dst)[q]          = *(uint4*)&hiw[q * 4];
#pragma unroll
        for (int q = 0; q < 8; q++) ((uint4*)(dst + 4096))[q] = *(uint4*)&low[q * 4];
    }
}

// ---------------- GRU recurrent kernel (mma.sync bf16, 3-pass hi/lo) ----------------
// SMEM: [0,153600) W_lo rows (400B stride); [153600, +2*25600) B double buffer:
//       each buf = hi plane 12800 (32 n x 400B) + lo plane 12800. k*2 bytes; h at k=64+j.
#define WLO_OFF 0
#define BB_OFF  153600
#define GRU_SMEM 204800

__global__ void __launch_bounds__(256, 1) gru_kernel() {
    extern __shared__ __align__(16) unsigned char smem[];
    const uint32_t sbase = smem_u32(smem);
    const int g   = blockIdx.x >> 6;
    const int sq  = blockIdx.x & 63;
    const int tid = threadIdx.x;
    const int w   = tid >> 5;
    const int lane = tid & 31;

    // stage W_hi into the W region, ldmatrix-load into registers
    {
        const uint4* src = (const uint4*)(g_whi + (size_t)g * 73728);
        for (int i = 0; i < 36; i++) {
            int idx = tid + i * 256;
            int row = idx / 24, u = idx % 24;
            *(uint4*)(smem + WLO_OFF + row * 400 + u * 16) = src[idx];
        }
    }
    __syncthreads();
    const uint32_t aRow = (uint32_t)(w * 48 + (lane & 15)) * 400 + ((lane >> 4) & 1) * 16;
    uint32_t wf[3][12][4];
#pragma unroll
    for (int mt = 0; mt < 3; mt++)
#pragma unroll
        for (int kt = 0; kt < 12; kt++)
            ldsm4(wf[mt][kt], sbase + WLO_OFF + aRow + mt * 6400 + kt * 32);
    __syncthreads();
    // overwrite with W_lo
    {
        const uint4* src = (const uint4*)(g_wlo + (size_t)g * 73728);
        for (int i = 0; i < 36; i++) {
            int idx = tid + i * 256;
            int row = idx / 24, u = idx % 24;
            *(uint4*)(smem + WLO_OFF + row * 400 + u * 16) = src[idx];
        }
    }
    // buf0: zero h regions (both planes), stage x step 0
    for (int i = tid; i < 1024; i += 256) {
        int pl = i >> 9, r = (i & 511) >> 4, u = i & 15;
        *(uint4*)(smem + BB_OFF + pl * 12800 + r * 400 + 128 + u * 16) = make_uint4(0, 0, 0, 0);
    }
    const uint4* xsrc = (const uint4*)(g_xn + ((size_t)(g * 64 + sq) * 256) * 8192);
    {
        uint4 v0 = xsrc[tid], v1 = xsrc[tid + 256];
        *(uint4*)(smem + BB_OFF + (tid >> 3) * 400 + (tid & 7) * 16) = v0;
        *(uint4*)(smem + BB_OFF + 12800 + (tid >> 3) * 400 + (tid & 7) * 16) = v1;
    }
    // biases for this thread's rows (j = w*16 + jw, +8)
    const int jw = lane >> 2;
    const float bR0 = g_bias[g * 512 + 0 + w * 16 + jw], bR1 = g_bias[g * 512 + 0 + w * 16 + jw + 8];
    const float bZ0 = g_bias[g * 512 + 128 + w * 16 + jw], bZ1 = g_bias[g * 512 + 128 + w * 16 + jw + 8];
    const float bI0 = g_bias[g * 512 + 256 + w * 16 + jw], bI1 = g_bias[g * 512 + 256 + w * 16 + jw + 8];
    const float bH0 = g_bias[g * 512 + 384 + w * 16 + jw], bH1 = g_bias[g * 512 + 384 + w * 16 + jw + 8];
    __syncthreads();

    const uint32_t bRow = (uint32_t)(lane & 7) * 400 + ((lane >> 3) & 1) * 16;

    for (int s = 0; s < 256; s++) {
        const uint32_t curOff = BB_OFF + (s & 1) * 25600;
        const uint32_t nxtOff = BB_OFF + ((s & 1) ^ 1) * 25600;
        const uint32_t cur = sbase + curOff;

        // prefetch next x (consumed after the mma passes)
        uint4 xv0, xv1;
        if (s < 255) {
            xv0 = xsrc[(size_t)(s + 1) * 512 + tid];
            xv1 = xsrc[(size_t)(s + 1) * 512 + tid + 256];
        }

        float aR[4][4], aZ[4][4], aNI[4][4], aNH[4][4];
#pragma unroll
        for (int nt = 0; nt < 4; nt++) {
            aR[nt][0] = bR0; aR[nt][1] = bR0; aR[nt][2] = bR1; aR[nt][3] = bR1;
            aZ[nt][0] = bZ0; aZ[nt][1] = bZ0; aZ[nt][2] = bZ1; aZ[nt][3] = bZ1;
            aNI[nt][0] = bI0; aNI[nt][1] = bI0; aNI[nt][2] = bI1; aNI[nt][3] = bI1;
            aNH[nt][0] = bH0; aNH[nt][1] = bH0; aNH[nt][2] = bH1; aNH[nt][3] = bH1;
        }

        // passes 1+2: B = hi plane; A = Whi (regs) and Wlo (streamed)
#pragma unroll
        for (int kt = 0; kt < 12; kt++) {
            uint32_t alo[3][4];
#pragma unroll
            for (int mt = 0; mt < 3; mt++)
                ldsm4(alo[mt], sbase + WLO_OFF + aRow + mt * 6400 + kt * 32);
#pragma unroll
            for (int nt = 0; nt < 4; nt++) {
                uint32_t bf[2];
                ldsm2(bf, cur + bRow + nt * 3200 + kt * 32);
                float* t2 = (kt < 4) ? aNI[nt] : aNH[nt];
                mma16816(aR[nt], wf[0][kt], bf);
                mma16816(aZ[nt], wf[1][kt], bf);
                mma16816(t2,     wf[2][kt], bf);
                mma16816(aR[nt], alo[0], bf);
                mma16816(aZ[nt], alo[1], bf);
                mma16816(t2,     alo[2], bf);
            }
        }
        // pass 3: B = lo plane; A = Whi (regs)
#pragma unroll
        for (int kt = 0; kt < 12; kt++) {
#pragma unroll
            for (int nt = 0; nt < 4; nt++) {
                uint32_t bf[2];
                ldsm2(bf, cur + 12800 + bRow + nt * 3200 + kt * 32);
                float* t2 = (kt < 4) ? aNI[nt] : aNH[nt];
                mma16816(aR[nt], wf[0][kt], bf);
                mma16816(aZ[nt], wf[1][kt], bf);
                mma16816(t2,     wf[2][kt], bf);
            }
        }

        // stage prefetched x into next buffer
        if (s < 255) {
            *(uint4*)(smem + nxtOff + (tid >> 3) * 400 + (tid & 7) * 16) = xv0;
            *(uint4*)(smem + nxtOff + 12800 + (tid >> 3) * 400 + (tid & 7) * 16) = xv1;
        }

        // epilogue: gate math, h write (hi+lo) into next buffer
#pragma unroll
        for (int nt = 0; nt < 4; nt++) {
#pragma unroll
            for (int p = 0; p < 4; p++) {
                const int n = nt * 8 + (lane & 3) * 2 + (p & 1);
                const int j = w * 16 + jw + ((p & 2) ? 8 : 0);
                const int hb = n * 400 + 128 + j * 2;
                float ho = __bfloat162float(*(__nv_bfloat16*)(smem + curOff + hb)) +
                           __bfloat162float(*(__nv_bfloat16*)(smem + curOff + 12800 + hb));
                float r  = siga(aR[nt][p]);
                float z  = siga(aZ[nt][p]);
                float nn = tanha(fmaf(r, aNH[nt][p], aNI[nt][p]));
                float h  = nn + z * (ho - nn);
                __nv_bfloat16 hi = __float2bfloat16(h);
                __nv_bfloat16 lo = __float2bfloat16(h - __bfloat162float(hi));
                *(__nv_bfloat16*)(smem + nxtOff + hb) = hi;
                *(__nv_bfloat16*)(smem + nxtOff + 12800 + hb) = lo;
                if (s == 255)
                    g_hout[((size_t)g * NSEQ + sq * 32 + n) * 128 + j] = h;
            }
        }
        __syncthreads();
    }
}

// ---------------- output projection + broadcast ----------------
__global__ void out_kernel(const float* __restrict__ Wp, const float* __restrict__ bp,
                           float* __restrict__ out) {
    __shared__ float s_vec[128];
    __shared__ float part_s[4][64];
    __shared__ float s_out[64];
    const int bt = blockIdx.x;
    const int b  = bt >> 8;
    const int t  = bt & 255;
    const int tid = threadIdx.x;
    const int nidx = b * 256 + t;

    if (tid < 128)
        s_vec[tid] = g_hout[(size_t)nidx * 128 + tid] +
                     g_hout[((size_t)NSEQ + nidx) * 128 + tid];
    __syncthreads();

    const int c = tid & 63, p = tid >> 6;
    float sum = 0.0f;
#pragma unroll
    for (int h = 0; h < 32; h++)
        sum = fmaf(Wp[c * 128 + p * 32 + h], s_vec[p * 32 + h], sum);
    part_s[p][c] = sum;
    __syncthreads();
    if (tid < 64)
        s_out[tid] = bp[tid] + part_s[0][tid] + part_s[1][tid] + part_s[2][tid] + part_s[3][tid];
    __syncthreads();

    float4* o4 = (float4*)out;
    const size_t base4 = ((size_t)b * 64) * 16384 + (size_t)t * 64;
    for (int e = tid; e < 4096; e += 256) {
        int c2 = e >> 6, f4 = e & 63;
        float v = s_out[c2];
        o4[base4 + (size_t)c2 * 16384 + f4] = make_float4(v, v, v, v);
    }
}

// ---------------- launcher ----------------
extern "C" void kernel_launch(void* const* d_in, const int* in_sizes, int n_in,
                              void* d_out, int out_size) {
    const float* x     = (const float*)d_in[0];
    const float* Wih_t = (const float*)d_in[1];
    const float* Whh_t = (const float*)d_in[2];
    const float* bih_t = (const float*)d_in[3];
    const float* bhh_t = (const float*)d_in[4];
    const float* Wih_f = (const float*)d_in[5];
    const float* Whh_f = (const float*)d_in[6];
    const float* bih_f = (const float*)d_in[7];
    const float* bhh_f = (const float*)d_in[8];
    const float* Wp    = (const float*)d_in[9];
    const float* bp    = (const float*)d_in[10];
    float* out = (float*)d_out;

    cudaFuncSetAttribute(gru_kernel, cudaFuncAttributeMaxDynamicSharedMemorySize, GRU_SMEM);
    cudaFuncSetAttribute(transpose_kernel, cudaFuncAttributeMaxDynamicSharedMemorySize, 65792);

    prep_kernel<<<(2 * 384 * 192 + 256 + 255) / 256, 256>>>(Wih_t, Whh_t, bih_t, bhh_t,
                                                            Wih_f, Whh_f, bih_f, bhh_f);
    transpose_kernel<<<8 * 32 * 8, 256, 65792>>>(x);
    gru_kernel<<<128, 256, GRU_SMEM>>>();
    out_kernel<<<2048, 256>>>(Wp, bp, out);
}

// round 7
// speedup vs baseline: 4.9286x; 1.3476x over previous
#include <cuda_runtime.h>
#include <cuda_fp16.h>
#include <stdint.h>

#define NSEQ 2048

// ---------------- device scratch ----------------
// per (g, sb, step) 8KB block: [plane hi/lo][n 32][k 64] fp16 (x part)
__device__ unsigned char g_xn[(size_t)2 * 64 * 256 * 8192];
__device__ __half g_wh16[2 * 384 * 192];   // fp16(W), permuted rows rp = w*48+sec*16+jj,
                                           // h-cols at 64+sigma(j)
__device__ float g_bias[2 * 4 * 128];      // [g][{br,bz,bni,bnh}][j]
__device__ float g_hout[2 * NSEQ * 128];

// SMEM layout (gru): W 384 rows x 400B = 153600; then B double buffer:
// buf = hi plane 32x400 (12800) + lo plane (12800); two bufs.
#define BB_OFF   153600
#define GRU_SMEM 204800

// ---------------- helpers ----------------
__device__ __forceinline__ uint32_t smem_u32(const void* p) {
    uint32_t a;
    asm("{ .reg .u64 t; cvta.to.shared.u64 t, %1; cvt.u32.u64 %0, t; }" : "=r"(a) : "l"(p));
    return a;
}
__device__ __forceinline__ float tanha(float x) {
    float y; asm("tanh.approx.f32 %0, %1;" : "=f"(y) : "f"(x)); return y;
}
__device__ __forceinline__ float siga(float x) { return 0.5f * tanha(0.5f * x) + 0.5f; }
__device__ __forceinline__ uint32_t pack_h2(__half a, __half b) {
    return (uint32_t)__half_as_ushort(a) | ((uint32_t)__half_as_ushort(b) << 16);
}
__device__ __forceinline__ void ldsm4(uint32_t* r, uint32_t addr) {
    asm volatile("ldmatrix.sync.aligned.m8n8.x4.shared.b16 {%0,%1,%2,%3}, [%4];"
        : "=r"(r[0]), "=r"(r[1]), "=r"(r[2]), "=r"(r[3]) : "r"(addr));
}
__device__ __forceinline__ void ldsm2(uint32_t* r, uint32_t addr) {
    asm volatile("ldmatrix.sync.aligned.m8n8.x2.shared.b16 {%0,%1}, [%2];"
        : "=r"(r[0]), "=r"(r[1]) : "r"(addr));
}
__device__ __forceinline__ void mma16816(float* c, const uint32_t* a, const uint32_t* b) {
    asm volatile("mma.sync.aligned.m16n8k16.row.col.f32.f16.f16.f32 "
        "{%0,%1,%2,%3}, {%4,%5,%6,%7}, {%8,%9}, {%0,%1,%2,%3};"
        : "+f"(c[0]), "+f"(c[1]), "+f"(c[2]), "+f"(c[3])
        : "r"(a[0]), "r"(a[1]), "r"(a[2]), "r"(a[3]), "r"(b[0]), "r"(b[1]));
}

// ---------------- prep: fp16 W (permuted) + fused biases ----------------
__global__ void prep_kernel(const float* __restrict__ Wih_t, const float* __restrict__ Whh_t,
                            const float* __restrict__ bih_t, const float* __restrict__ bhh_t,
                            const float* __restrict__ Wih_f, const float* __restrict__ Whh_f,
                            const float* __restrict__ bih_f, const float* __restrict__ bhh_f) {
    int idx = blockIdx.x * blockDim.x + threadIdx.x;
    const int NW = 2 * 384 * 192;
    if (idx < NW) {
        int k  = idx % 192;
        int rp = (idx / 192) % 384;
        int g  = idx / (384 * 192);
        int w = rp / 48, rem = rp % 48, sec = rem / 16, jj = rem % 16;
        int orig = sec * 128 + w * 16 + jj;
        const float* Wih = g ? Wih_f : Wih_t;
        const float* Whh = g ? Whh_f : Whh_t;
        float v;
        if (k < 64) {
            v = Wih[orig * 64 + k];
        } else {
            int kk = k - 64;
            int w2 = kk >> 4, p = kk & 15;
            int u  = (p >> 1) + ((p & 1) << 3);     // inverse sigma
            v = Whh[orig * 128 + w2 * 16 + u];
        }
        g_wh16[idx] = __float2half_rn(v);
    } else if (idx < NW + 256) {
        int t = idx - NW;
        int g = t >> 7, j = t & 127;
        const float* bih = g ? bih_f : bih_t;
        const float* bhh = g ? bhh_f : bhh_t;
        float* dst = &g_bias[g * 512];
        dst[0 * 128 + j] = bih[j] + bhh[j];
        dst[1 * 128 + j] = bih[128 + j] + bhh[128 + j];
        dst[2 * 128 + j] = bih[256 + j];
        dst[3 * 128 + j] = bhh[256 + j];
    }
}

// ---------------- transpose: n-major fp16 hi/lo x images ----------------
__global__ void transpose_kernel(const float* __restrict__ x) {
    extern __shared__ float slab[];
    const int bx = blockIdx.x;
    const int fb = bx & 7;
    const int tb = (bx >> 3) & 31;
    const int b  = bx >> 8;
    const int f0 = fb * 32, t0 = tb * 8;
    const int tid = threadIdx.x;
#pragma unroll
    for (int i = 0; i < 16; i++) {
        int idx = tid + i * 256;
        int f4 = idx & 7, tt = (idx >> 3) & 7, c = idx >> 6;
        float4 v = ((const float4*)x)[(((size_t)(b * 64 + c) * 256 + t0 + tt) << 6) + (f0 >> 2) + f4];
        float* d = &slab[c * 257 + tt * 32 + f4 * 4];
        d[0] = v.x; d[1] = v.y; d[2] = v.z; d[3] = v.w;
    }
    __syncthreads();
    const int tt = tid >> 5, ff = tid & 31;
    const int t = t0 + tt, f = f0 + ff;
    uint32_t hiw[32], low[32];
#pragma unroll
    for (int q = 0; q < 32; q++) {
        float v0 = slab[(2 * q) * 257 + tt * 32 + ff];
        float v1 = slab[(2 * q + 1) * 257 + tt * 32 + ff];
        __half h0 = __float2half_rn(v0), h1 = __float2half_rn(v1);
        __half l0 = __float2half_rn(v0 - __half2float(h0));
        __half l1 = __float2half_rn(v1 - __half2float(h1));
        hiw[q] = pack_h2(h0, h1);
        low[q] = pack_h2(l0, l1);
    }
    {
        unsigned char* dst = g_xn + ((size_t)(0 * 64 + b * 8 + fb) * 256 + t) * 8192 + ff * 128;
#pragma unroll
        for (int q = 0; q < 8; q++) ((uint4*)dst)[q]          = *(uint4*)&hiw[q * 4];
#pragma unroll
        for (int q = 0; q < 8; q++) ((uint4*)(dst + 4096))[q] = *(uint4*)&low[q * 4];
    }
    {
        unsigned char* dst = g_xn + ((size_t)(1 * 64 + b * 8 + (t >> 5)) * 256 + f) * 8192 + (t & 31) * 128;
#pragma unroll
        for (int q = 0; q < 8; q++) ((uint4*)dst)[q]          = *(uint4*)&hiw[q * 4];
#pragma unroll
        for (int q = 0; q < 8; q++) ((uint4*)(dst + 4096))[q] = *(uint4*)&low[q * 4];
    }
}

// ---------------- GRU recurrent kernel (mma.sync fp16, 2 passes hi/lo B) ----------------
__global__ void __launch_bounds__(256, 1) gru_kernel() {
    extern __shared__ __align__(16) unsigned char smem[];
    const uint32_t sbase = smem_u32(smem);
    const int g   = blockIdx.x >> 6;
    const int sq  = blockIdx.x & 63;
    const int tid = threadIdx.x;
    const int w   = tid >> 5;
    const int lane = tid & 31;

    // stage W into smem (400B row stride)
    {
        const uint4* src = (const uint4*)(g_wh16 + (size_t)g * 73728);
        for (int i = 0; i < 36; i++) {
            int idx = tid + i * 256;
            int row = idx / 24, u = idx % 24;
            *(uint4*)(smem + row * 400 + u * 16) = src[idx];
        }
    }
    // buf0: zero h regions (both planes), stage x step 0
    for (int i = tid; i < 1024; i += 256) {
        int pl = i >> 9, r = (i & 511) >> 4, u = i & 15;
        *(uint4*)(smem + BB_OFF + pl * 12800 + r * 400 + 128 + u * 16) = make_uint4(0, 0, 0, 0);
    }
    const uint4* xsrc = (const uint4*)(g_xn + ((size_t)(g * 64 + sq) * 256) * 8192);
    {
        uint4 v0 = xsrc[tid], v1 = xsrc[tid + 256];
        *(uint4*)(smem + BB_OFF + (tid >> 3) * 400 + (tid & 7) * 16) = v0;
        *(uint4*)(smem + BB_OFF + 12800 + (tid >> 3) * 400 + (tid & 7) * 16) = v1;
    }
    const int jw = lane >> 2;
    const float bR0 = g_bias[g * 512 + 0 + w * 16 + jw], bR1 = g_bias[g * 512 + 0 + w * 16 + jw + 8];
    const float bZ0 = g_bias[g * 512 + 128 + w * 16 + jw], bZ1 = g_bias[g * 512 + 128 + w * 16 + jw + 8];
    const float bI0 = g_bias[g * 512 + 256 + w * 16 + jw], bI1 = g_bias[g * 512 + 256 + w * 16 + jw + 8];
    const float bH0 = g_bias[g * 512 + 384 + w * 16 + jw], bH1 = g_bias[g * 512 + 384 + w * 16 + jw + 8];
    __syncthreads();

    const uint32_t aRow = sbase + (uint32_t)(w * 48 + (lane & 15)) * 400 + ((lane >> 4) & 1) * 16;
    const uint32_t bRow = (uint32_t)(lane & 7) * 400 + ((lane >> 3) & 1) * 16;

    float hold[16];
#pragma unroll
    for (int i = 0; i < 16; i++) hold[i] = 0.0f;

    for (int s = 0; s < 256; s++) {
        const uint32_t curOff = BB_OFF + (s & 1) * 25600;
        const uint32_t nxtOff = BB_OFF + ((s & 1) ^ 1) * 25600;
        const uint32_t cur = sbase + curOff;

        uint4 xv0, xv1;
        if (s < 255) {
            xv0 = xsrc[(size_t)(s + 1) * 512 + tid];
            xv1 = xsrc[(size_t)(s + 1) * 512 + tid + 256];
        }

        float aR[4][4], aZ[4][4], aNI[4][4], aNH[4][4];
#pragma unroll
        for (int nt = 0; nt < 4; nt++) {
            aR[nt][0] = bR0; aR[nt][1] = bR0; aR[nt][2] = bR1; aR[nt][3] = bR1;
            aZ[nt][0] = bZ0; aZ[nt][1] = bZ0; aZ[nt][2] = bZ1; aZ[nt][3] = bZ1;
            aNI[nt][0] = bI0; aNI[nt][1] = bI0; aNI[nt][2] = bI1; aNI[nt][3] = bI1;
            aNH[nt][0] = bH0; aNH[nt][1] = bH0; aNH[nt][2] = bH1; aNH[nt][3] = bH1;
        }

#pragma unroll
        for (int kt = 0; kt < 12; kt++) {
            uint32_t af[3][4];
#pragma unroll
            for (int mt = 0; mt < 3; mt++)
                ldsm4(af[mt], aRow + mt * 6400 + kt * 32);
            uint32_t bhi[4][2], blo[4][2];
#pragma unroll
            for (int nt = 0; nt < 4; nt++) {
                ldsm2(bhi[nt], cur + bRow + nt * 3200 + kt * 32);
                ldsm2(blo[nt], cur + 12800 + bRow + nt * 3200 + kt * 32);
            }
#pragma unroll
            for (int nt = 0; nt < 4; nt++) {
                float* t2 = (kt < 4) ? aNI[nt] : aNH[nt];
                mma16816(aR[nt], af[0], bhi[nt]);
                mma16816(aZ[nt], af[1], bhi[nt]);
                mma16816(t2,     af[2], bhi[nt]);
            }
#pragma unroll
            for (int nt = 0; nt < 4; nt++) {
                float* t2 = (kt < 4) ? aNI[nt] : aNH[nt];
                mma16816(aR[nt], af[0], blo[nt]);
                mma16816(aZ[nt], af[1], blo[nt]);
                mma16816(t2,     af[2], blo[nt]);
            }
        }

        // stage prefetched x into next buffer
        if (s < 255) {
            *(uint4*)(smem + nxtOff + (tid >> 3) * 400 + (tid & 7) * 16) = xv0;
            *(uint4*)(smem + nxtOff + 12800 + (tid >> 3) * 400 + (tid & 7) * 16) = xv1;
        }

        // epilogue: gates, h update (regs), paired fp16 hi/lo stores via sigma layout
#pragma unroll
        for (int nt = 0; nt < 4; nt++) {
#pragma unroll
            for (int q = 0; q < 2; q++) {
                float hv[2];
#pragma unroll
                for (int t2 = 0; t2 < 2; t2++) {
                    const int p = q + t2 * 2;
                    const int idx = nt * 4 + p;
                    float r  = siga(aR[nt][p]);
                    float z  = siga(aZ[nt][p]);
                    float nn = tanha(fmaf(r, aNH[nt][p], aNI[nt][p]));
                    float h  = nn + z * (hold[idx] - nn);
                    hold[idx] = h;
                    hv[t2] = h;
                    if (s == 255) {
                        const int n = nt * 8 + (lane & 3) * 2 + q;
                        const int j = w * 16 + jw + t2 * 8;
                        g_hout[((size_t)g * NSEQ + sq * 32 + n) * 128 + j] = h;
                    }
                }
                const int n = nt * 8 + (lane & 3) * 2 + q;
                __half h0 = __float2half_rn(hv[0]);
                __half h1 = __float2half_rn(hv[1]);
                __half l0 = __float2half_rn(hv[0] - __half2float(h0));
                __half l1 = __float2half_rn(hv[1] - __half2float(h1));
                const uint32_t hb = nxtOff + n * 400 + 128 + w * 32 + jw * 4;
                *(uint32_t*)(smem + hb)          = pack_h2(h0, h1);
                *(uint32_t*)(smem + hb + 12800)  = pack_h2(l0, l1);
            }
        }
        __syncthreads();
    }
}

// ---------------- output projection + broadcast ----------------
__global__ void out_kernel(const float* __restrict__ Wp, const float* __restrict__ bp,
                           float* __restrict__ out) {
    __shared__ float s_vec[128];
    __shared__ float part_s[4][64];
    __shared__ float s_out[64];
    const int bt = blockIdx.x;
    const int b  = bt >> 8;
    const int t  = bt & 255;
    const int tid = threadIdx.x;
    const int nidx = b * 256 + t;

    if (tid < 128)
        s_vec[tid] = g_hout[(size_t)nidx * 128 + tid] +
                     g_hout[((size_t)NSEQ + nidx) * 128 + tid];
    __syncthreads();

    const int c = tid & 63, p = tid >> 6;
    float sum = 0.0f;
#pragma unroll
    for (int h = 0; h < 32; h++)
        sum = fmaf(Wp[c * 128 + p * 32 + h], s_vec[p * 32 + h], sum);
    part_s[p][c] = sum;
    __syncthreads();
    if (tid < 64)
        s_out[tid] = bp[tid] + part_s[0][tid] + part_s[1][tid] + part_s[2][tid] + part_s[3][tid];
    __syncthreads();

    float4* o4 = (float4*)out;
    const size_t base4 = ((size_t)b * 64) * 16384 + (size_t)t * 64;
    for (int e = tid; e < 4096; e += 256) {
        int c2 = e >> 6, f4 = e & 63;
        float v = s_out[c2];
        o4[base4 + (size_t)c2 * 16384 + f4] = make_float4(v, v, v, v);
    }
}

// ---------------- launcher ----------------
extern "C" void kernel_launch(void* const* d_in, const int* in_sizes, int n_in,
                              void* d_out, int out_size) {
    const float* x     = (const float*)d_in[0];
    const float* Wih_t = (const float*)d_in[1];
    const float* Whh_t = (const float*)d_in[2];
    const float* bih_t = (const float*)d_in[3];
    const float* bhh_t = (const float*)d_in[4];
    const float* Wih_f = (const float*)d_in[5];
    const float* Whh_f = (const float*)d_in[6];
    const float* bih_f = (const float*)d_in[7];
    const float* bhh_f = (const float*)d_in[8];
    const float* Wp    = (const float*)d_in[9];
    const float* bp    = (const float*)d_in[10];
    float* out = (float*)d_out;

    cudaFuncSetAttribute(gru_kernel, cudaFuncAttributeMaxDynamicSharedMemorySize, GRU_SMEM);
    cudaFuncSetAttribute(transpose_kernel, cudaFuncAttributeMaxDynamicSharedMemorySize, 65792);

    prep_kernel<<<(2 * 384 * 192 + 256 + 255) / 256, 256>>>(Wih_t, Whh_t, bih_t, bhh_t,
                                                            Wih_f, Whh_f, bih_f, bhh_f);
    transpose_kernel<<<8 * 32 * 8, 256, 65792>>>(x);
    gru_kernel<<<128, 256, GRU_SMEM>>>();
    out_kernel<<<2048, 256>>>(Wp, bp, out);
}

// round 8
// speedup vs baseline: 7.8043x; 1.5835x over previous
#include <cuda_runtime.h>
#include <cuda_fp16.h>
#include <stdint.h>

#define NSEQ 2048

// ---------------- device scratch ----------------
// per (g, sb, step) 4KB block: [n 32][k 64] fp16 (x part, hi only)
__device__ unsigned char g_xn[(size_t)2 * 64 * 256 * 4096];
__device__ __half g_wh16[2 * 384 * 192];   // fp16(W), permuted rows rp = w*48+sec*16+jj,
                                           // h-cols at 64+sigma(j)
__device__ float g_bias[2 * 4 * 128];      // [g][{br,bz,bni,bnh}][j]
__device__ float g_hout[2 * NSEQ * 128];

// SMEM layout (gru): W 384 rows x 400B = 153600; then B double buffer (12800 each).
#define BB_OFF   153600
#define GRU_SMEM 179200

// ---------------- helpers ----------------
__device__ __forceinline__ uint32_t smem_u32(const void* p) {
    uint32_t a;
    asm("{ .reg .u64 t; cvta.to.shared.u64 t, %1; cvt.u32.u64 %0, t; }" : "=r"(a) : "l"(p));
    return a;
}
__device__ __forceinline__ float tanha(float x) {
    float y; asm("tanh.approx.f32 %0, %1;" : "=f"(y) : "f"(x)); return y;
}
__device__ __forceinline__ float siga(float x) { return 0.5f * tanha(0.5f * x) + 0.5f; }
__device__ __forceinline__ uint32_t pack_h2(__half a, __half b) {
    return (uint32_t)__half_as_ushort(a) | ((uint32_t)__half_as_ushort(b) << 16);
}
__device__ __forceinline__ void ldsm4(uint32_t* r, uint32_t addr) {
    asm volatile("ldmatrix.sync.aligned.m8n8.x4.shared.b16 {%0,%1,%2,%3}, [%4];"
        : "=r"(r[0]), "=r"(r[1]), "=r"(r[2]), "=r"(r[3]) : "r"(addr));
}
__device__ __forceinline__ void ldsm2(uint32_t* r, uint32_t addr) {
    asm volatile("ldmatrix.sync.aligned.m8n8.x2.shared.b16 {%0,%1}, [%2];"
        : "=r"(r[0]), "=r"(r[1]) : "r"(addr));
}
__device__ __forceinline__ void mma16816(float* c, const uint32_t* a, const uint32_t* b) {
    asm volatile("mma.sync.aligned.m16n8k16.row.col.f32.f16.f16.f32 "
        "{%0,%1,%2,%3}, {%4,%5,%6,%7}, {%8,%9}, {%0,%1,%2,%3};"
        : "+f"(c[0]), "+f"(c[1]), "+f"(c[2]), "+f"(c[3])
        : "r"(a[0]), "r"(a[1]), "r"(a[2]), "r"(a[3]), "r"(b[0]), "r"(b[1]));
}

// ---------------- prep: fp16 W (permuted) + fused biases ----------------
__global__ void prep_kernel(const float* __restrict__ Wih_t, const float* __restrict__ Whh_t,
                            const float* __restrict__ bih_t, const float* __restrict__ bhh_t,
                            const float* __restrict__ Wih_f, const float* __restrict__ Whh_f,
                            const float* __restrict__ bih_f, const float* __restrict__ bhh_f) {
    int idx = blockIdx.x * blockDim.x + threadIdx.x;
    const int NW = 2 * 384 * 192;
    if (idx < NW) {
        int k  = idx % 192;
        int rp = (idx / 192) % 384;
        int g  = idx / (384 * 192);
        int w = rp / 48, rem = rp % 48, sec = rem / 16, jj = rem % 16;
        int orig = sec * 128 + w * 16 + jj;
        const float* Wih = g ? Wih_f : Wih_t;
        const float* Whh = g ? Whh_f : Whh_t;
        float v;
        if (k < 64) {
            v = Wih[orig * 64 + k];
        } else {
            int kk = k - 64;
            int w2 = kk >> 4, p = kk & 15;
            int u  = (p >> 1) + ((p & 1) << 3);     // inverse sigma
            v = Whh[orig * 128 + w2 * 16 + u];
        }
        g_wh16[idx] = __float2half_rn(v);
    } else if (idx < NW + 256) {
        int t = idx - NW;
        int g = t >> 7, j = t & 127;
        const float* bih = g ? bih_f : bih_t;
        const float* bhh = g ? bhh_f : bhh_t;
        float* dst = &g_bias[g * 512];
        dst[0 * 128 + j] = bih[j] + bhh[j];
        dst[1 * 128 + j] = bih[128 + j] + bhh[128 + j];
        dst[2 * 128 + j] = bih[256 + j];
        dst[3 * 128 + j] = bhh[256 + j];
    }
}

// ---------------- transpose: n-major fp16 x images ----------------
__global__ void transpose_kernel(const float* __restrict__ x) {
    extern __shared__ float slab[];
    const int bx = blockIdx.x;
    const int fb = bx & 7;
    const int tb = (bx >> 3) & 31;
    const int b  = bx >> 8;
    const int f0 = fb * 32, t0 = tb * 8;
    const int tid = threadIdx.x;
#pragma unroll
    for (int i = 0; i < 16; i++) {
        int idx = tid + i * 256;
        int f4 = idx & 7, tt = (idx >> 3) & 7, c = idx >> 6;
        float4 v = ((const float4*)x)[(((size_t)(b * 64 + c) * 256 + t0 + tt) << 6) + (f0 >> 2) + f4];
        float* d = &slab[c * 257 + tt * 32 + f4 * 4];
        d[0] = v.x; d[1] = v.y; d[2] = v.z; d[3] = v.w;
    }
    __syncthreads();
    const int tt = tid >> 5, ff = tid & 31;
    const int t = t0 + tt, f = f0 + ff;
    uint32_t hiw[32];
#pragma unroll
    for (int q = 0; q < 32; q++) {
        float v0 = slab[(2 * q) * 257 + tt * 32 + ff];
        float v1 = slab[(2 * q + 1) * 257 + tt * 32 + ff];
        hiw[q] = pack_h2(__float2half_rn(v0), __float2half_rn(v1));
    }
    {
        unsigned char* dst = g_xn + ((size_t)(0 * 64 + b * 8 + fb) * 256 + t) * 4096 + ff * 128;
#pragma unroll
        for (int q = 0; q < 8; q++) ((uint4*)dst)[q] = *(uint4*)&hiw[q * 4];
    }
    {
        unsigned char* dst = g_xn + ((size_t)(1 * 64 + b * 8 + (t >> 5)) * 256 + f) * 4096 + (t & 31) * 128;
#pragma unroll
        for (int q = 0; q < 8; q++) ((uint4*)dst)[q] = *(uint4*)&hiw[q * 4];
    }
}

// ---------------- GRU recurrent kernel (mma.sync fp16, single pass) ----------------
__global__ void __launch_bounds__(256, 1) gru_kernel() {
    extern __shared__ __align__(16) unsigned char smem[];
    const uint32_t sbase = smem_u32(smem);
    const int g   = blockIdx.x >> 6;
    const int sq  = blockIdx.x & 63;
    const int tid = threadIdx.x;
    const int w   = tid >> 5;
    const int lane = tid & 31;

    // stage W into smem (400B row stride)
    {
        const uint4* src = (const uint4*)(g_wh16 + (size_t)g * 73728);
        for (int i = 0; i < 36; i++) {
            int idx = tid + i * 256;
            int row = idx / 24, u = idx % 24;
            *(uint4*)(smem + row * 400 + u * 16) = src[idx];
        }
    }
    // buf0: zero h region, stage x step 0
    for (int i = tid; i < 512; i += 256) {
        int r = i >> 4, u = i & 15;
        *(uint4*)(smem + BB_OFF + r * 400 + 128 + u * 16) = make_uint4(0, 0, 0, 0);
    }
    const uint4* xsrc = (const uint4*)(g_xn + ((size_t)(g * 64 + sq) * 256) * 4096);
    {
        uint4 v0 = xsrc[tid];
        *(uint4*)(smem + BB_OFF + (tid >> 3) * 400 + (tid & 7) * 16) = v0;
    }
    const int jw = lane >> 2;
    const float bR0 = g_bias[g * 512 + 0 + w * 16 + jw], bR1 = g_bias[g * 512 + 0 + w * 16 + jw + 8];
    const float bZ0 = g_bias[g * 512 + 128 + w * 16 + jw], bZ1 = g_bias[g * 512 + 128 + w * 16 + jw + 8];
    const float bI0 = g_bias[g * 512 + 256 + w * 16 + jw], bI1 = g_bias[g * 512 + 256 + w * 16 + jw + 8];
    const float bH0 = g_bias[g * 512 + 384 + w * 16 + jw], bH1 = g_bias[g * 512 + 384 + w * 16 + jw + 8];
    __syncthreads();

    const uint32_t aRow = sbase + (uint32_t)(w * 48 + (lane & 15)) * 400 + ((lane >> 4) & 1) * 16;
    const uint32_t bRow = (uint32_t)(lane & 7) * 400 + ((lane >> 3) & 1) * 16;

    float hold[16];
#pragma unroll
    for (int i = 0; i < 16; i++) hold[i] = 0.0f;

    for (int s = 0; s < 256; s++) {
        const uint32_t curOff = BB_OFF + (s & 1) * 12800;
        const uint32_t nxtOff = BB_OFF + ((s & 1) ^ 1) * 12800;
        const uint32_t cur = sbase + curOff;

        uint4 xv0;
        if (s < 255) xv0 = xsrc[(size_t)(s + 1) * 256 + tid];

        float aR[4][4], aZ[4][4], aNI[4][4], aNH[4][4];
#pragma unroll
        for (int nt = 0; nt < 4; nt++) {
            aR[nt][0] = bR0; aR[nt][1] = bR0; aR[nt][2] = bR1; aR[nt][3] = bR1;
            aZ[nt][0] = bZ0; aZ[nt][1] = bZ0; aZ[nt][2] = bZ1; aZ[nt][3] = bZ1;
            aNI[nt][0] = bI0; aNI[nt][1] = bI0; aNI[nt][2] = bI1; aNI[nt][3] = bI1;
            aNH[nt][0] = bH0; aNH[nt][1] = bH0; aNH[nt][2] = bH1; aNH[nt][3] = bH1;
        }

#pragma unroll
        for (int kt = 0; kt < 12; kt++) {
            uint32_t af[3][4];
#pragma unroll
            for (int mt = 0; mt < 3; mt++)
                ldsm4(af[mt], aRow + mt * 6400 + kt * 32);
            uint32_t bhi[4][2];
#pragma unroll
            for (int nt = 0; nt < 4; nt++)
                ldsm2(bhi[nt], cur + bRow + nt * 3200 + kt * 32);
#pragma unroll
            for (int nt = 0; nt < 4; nt++) {
                float* t2 = (kt < 4) ? aNI[nt] : aNH[nt];
                mma16816(aR[nt], af[0], bhi[nt]);
                mma16816(aZ[nt], af[1], bhi[nt]);
                mma16816(t2,     af[2], bhi[nt]);
            }
        }

        // stage prefetched x into next buffer
        if (s < 255)
            *(uint4*)(smem + nxtOff + (tid >> 3) * 400 + (tid & 7) * 16) = xv0;

        // epilogue: gates, h update (regs), paired fp16 stores via sigma layout
#pragma unroll
        for (int nt = 0; nt < 4; nt++) {
#pragma unroll
            for (int q = 0; q < 2; q++) {
                float hv[2];
#pragma unroll
                for (int t2 = 0; t2 < 2; t2++) {
                    const int p = q + t2 * 2;
                    const int idx = nt * 4 + p;
                    float r  = siga(aR[nt][p]);
                    float z  = siga(aZ[nt][p]);
                    float nn = tanha(fmaf(r, aNH[nt][p], aNI[nt][p]));
                    float h  = nn + z * (hold[idx] - nn);
                    hold[idx] = h;
                    hv[t2] = h;
                    if (s == 255) {
                        const int n = nt * 8 + (lane & 3) * 2 + q;
                        const int j = w * 16 + jw + t2 * 8;
                        g_hout[((size_t)g * NSEQ + sq * 32 + n) * 128 + j] = h;
                    }
                }
                const int n = nt * 8 + (lane & 3) * 2 + q;
                const uint32_t hb = nxtOff + n * 400 + 128 + w * 32 + jw * 4;
                *(uint32_t*)(smem + hb) = pack_h2(__float2half_rn(hv[0]), __float2half_rn(hv[1]));
            }
        }
        __syncthreads();
    }
}

// ---------------- output projection + broadcast ----------------
__global__ void out_kernel(const float* __restrict__ Wp, const float* __restrict__ bp,
                           float* __restrict__ out) {
    __shared__ float s_vec[128];
    __shared__ float part_s[4][64];
    __shared__ float s_out[64];
    const int bt = blockIdx.x;
    const int b  = bt >> 8;
    const int t  = bt & 255;
    const int tid = threadIdx.x;
    const int nidx = b * 256 + t;

    if (tid < 128)
        s_vec[tid] = g_hout[(size_t)nidx * 128 + tid] +
                     g_hout[((size_t)NSEQ + nidx) * 128 + tid];
    __syncthreads();

    const int c = tid & 63, p = tid >> 6;
    float sum = 0.0f;
#pragma unroll
    for (int h = 0; h < 32; h++)
        sum = fmaf(Wp[c * 128 + p * 32 + h], s_vec[p * 32 + h], sum);
    part_s[p][c] = sum;
    __syncthreads();
    if (tid < 64)
        s_out[tid] = bp[tid] + part_s[0][tid] + part_s[1][tid] + part_s[2][tid] + part_s[3][tid];
    __syncthreads();

    float4* o4 = (float4*)out;
    const size_t base4 = ((size_t)b * 64) * 16384 + (size_t)t * 64;
    for (int e = tid; e < 4096; e += 256) {
        int c2 = e >> 6, f4 = e & 63;
        float v = s_out[c2];
        o4[base4 + (size_t)c2 * 16384 + f4] = make_float4(v, v, v, v);
    }
}

// ---------------- launcher ----------------
extern "C" void kernel_launch(void* const* d_in, const int* in_sizes, int n_in,
                              void* d_out, int out_size) {
    const float* x     = (const float*)d_in[0];
    const float* Wih_t = (const float*)d_in[1];
    const float* Whh_t = (const float*)d_in[2];
    const float* bih_t = (const float*)d_in[3];
    const float* bhh_t = (const float*)d_in[4];
    const float* Wih_f = (const float*)d_in[5];
    const float* Whh_f = (const float*)d_in[6];
    const float* bih_f = (const float*)d_in[7];
    const float* bhh_f = (const float*)d_in[8];
    const float* Wp    = (const float*)d_in[9];
    const float* bp    = (const float*)d_in[10];
    float* out = (float*)d_out;

    cudaFuncSetAttribute(gru_kernel, cudaFuncAttributeMaxDynamicSharedMemorySize, GRU_SMEM);
    cudaFuncSetAttribute(transpose_kernel, cudaFuncAttributeMaxDynamicSharedMemorySize, 65792);

    prep_kernel<<<(2 * 384 * 192 + 256 + 255) / 256, 256>>>(Wih_t, Whh_t, bih_t, bhh_t,
                                                            Wih_f, Whh_f, bih_f, bhh_f);
    transpose_kernel<<<8 * 32 * 8, 256, 65792>>>(x);
    gru_kernel<<<128, 256, GRU_SMEM>>>();
    out_kernel<<<2048, 256>>>(Wp, bp, out);
}

// round 10
// speedup vs baseline: 7.9849x; 1.0231x over previous
#include <cuda_runtime.h>
#include <cuda_fp16.h>
#include <stdint.h>

#define NSEQ 2048

// ---------------- device scratch ----------------
// per (g, sb, step) 4KB block: [n 32][k 64] fp16 (x part)
__device__ unsigned char g_xn[(size_t)2 * 64 * 256 * 4096];
__device__ __half g_wh16[2 * 384 * 192];   // fp16(W), permuted rows rp = w*48+sec*16+jj,
                                           // h-cols at 64+sigma(j)
__device__ float g_bias[2 * 4 * 128];      // [g][{br,bz,bni,bnh}][j]
__device__ float g_hout[2 * NSEQ * 128];

// SMEM layout (gru): W 384x400B = 153600; x triple buffer (32x144B = 4608 each);
// h double buffer (32x272B = 8704 each).
#define XBUF_OFF    153600
#define XBUF_STRIDE 144
#define XBUF_SZ     4608
#define HBUF_OFF    167424
#define HBUF_STRIDE 272
#define HBUF_SZ     8704
#define GRU_SMEM    184832

// ---------------- helpers ----------------
__device__ __forceinline__ uint32_t smem_u32(const void* p) {
    uint32_t a;
    asm("{ .reg .u64 t; cvta.to.shared.u64 t, %1; cvt.u32.u64 %0, t; }" : "=r"(a) : "l"(p));
    return a;
}
__device__ __forceinline__ float tanha(float x) {
    float y; asm("tanh.approx.f32 %0, %1;" : "=f"(y) : "f"(x)); return y;
}
__device__ __forceinline__ float siga(float x) { return 0.5f * tanha(0.5f * x) + 0.5f; }
__device__ __forceinline__ uint32_t pack_h2(__half a, __half b) {
    return (uint32_t)__half_as_ushort(a) | ((uint32_t)__half_as_ushort(b) << 16);
}
__device__ __forceinline__ void ldsm4(uint32_t* r, uint32_t addr) {
    asm volatile("ldmatrix.sync.aligned.m8n8.x4.shared.b16 {%0,%1,%2,%3}, [%4];"
        : "=r"(r[0]), "=r"(r[1]), "=r"(r[2]), "=r"(r[3]) : "r"(addr));
}
__device__ __forceinline__ void ldsm2(uint32_t* r, uint32_t addr) {
    asm volatile("ldmatrix.sync.aligned.m8n8.x2.shared.b16 {%0,%1}, [%2];"
        : "=r"(r[0]), "=r"(r[1]) : "r"(addr));
}
__device__ __forceinline__ void mma16816(float* c, const uint32_t* a, const uint32_t* b) {
    asm volatile("mma.sync.aligned.m16n8k16.row.col.f32.f16.f16.f32 "
        "{%0,%1,%2,%3}, {%4,%5,%6,%7}, {%8,%9}, {%0,%1,%2,%3};"
        : "+f"(c[0]), "+f"(c[1]), "+f"(c[2]), "+f"(c[3])
        : "r"(a[0]), "r"(a[1]), "r"(a[2]), "r"(a[3]), "r"(b[0]), "r"(b[1]));
}

// ---------------- prep: fp16 W (permuted) + fused biases ----------------
__global__ void prep_kernel(const float* __restrict__ Wih_t, const float* __restrict__ Whh_t,
                            const float* __restrict__ bih_t, const float* __restrict__ bhh_t,
                            const float* __restrict__ Wih_f, const float* __restrict__ Whh_f,
                            const float* __restrict__ bih_f, const float* __restrict__ bhh_f) {
    int idx = blockIdx.x * blockDim.x + threadIdx.x;
    const int NW = 2 * 384 * 192;
    if (idx < NW) {
        int k  = idx % 192;
        int rp = (idx / 192) % 384;
        int g  = idx / (384 * 192);
        int w = rp / 48, rem = rp % 48, sec = rem / 16, jj = rem % 16;
        int orig = sec * 128 + w * 16 + jj;
        const float* Wih = g ? Wih_f : Wih_t;
        const float* Whh = g ? Whh_f : Whh_t;
        float v;
        if (k < 64) {
            v = Wih[orig * 64 + k];
        } else {
            int kk = k - 64;
            int w2 = kk >> 4, p = kk & 15;
            int u  = (p >> 1) + ((p & 1) << 3);     // inverse sigma
            v = Whh[orig * 128 + w2 * 16 + u];
        }
        g_wh16[idx] = __float2half_rn(v);
    } else if (idx < NW + 256) {
        int t = idx - NW;
        int g = t >> 7, j = t & 127;
        const float* bih = g ? bih_f : bih_t;
        const float* bhh = g ? bhh_f : bhh_t;
        float* dst = &g_bias[g * 512];
        dst[0 * 128 + j] = bih[j] + bhh[j];
        dst[1 * 128 + j] = bih[128 + j] + bhh[128 + j];
        dst[2 * 128 + j] = bih[256 + j];
        dst[3 * 128 + j] = bhh[256 + j];
    }
}

// ---------------- transpose: n-major fp16 x images ----------------
__global__ void transpose_kernel(const float* __restrict__ x) {
    extern __shared__ float slab[];
    const int bx = blockIdx.x;
    const int fb = bx & 7;
    const int tb = (bx >> 3) & 31;
    const int b  = bx >> 8;
    const int f0 = fb * 32, t0 = tb * 8;
    const int tid = threadIdx.x;
#pragma unroll
    for (int i = 0; i < 16; i++) {
        int idx = tid + i * 256;
        int f4 = idx & 7, tt = (idx >> 3) & 7, c = idx >> 6;
        float4 v = ((const float4*)x)[(((size_t)(b * 64 + c) * 256 + t0 + tt) << 6) + (f0 >> 2) + f4];
        float* d = &slab[c * 257 + tt * 32 + f4 * 4];
        d[0] = v.x; d[1] = v.y; d[2] = v.z; d[3] = v.w;
    }
    __syncthreads();
    const int tt = tid >> 5, ff = tid & 31;
    const int t = t0 + tt, f = f0 + ff;
    uint32_t hiw[32];
#pragma unroll
    for (int q = 0; q < 32; q++) {
        float v0 = slab[(2 * q) * 257 + tt * 32 + ff];
        float v1 = slab[(2 * q + 1) * 257 + tt * 32 + ff];
        hiw[q] = pack_h2(__float2half_rn(v0), __float2half_rn(v1));
    }
    {
        unsigned char* dst = g_xn + ((size_t)(0 * 64 + b * 8 + fb) * 256 + t) * 4096 + ff * 128;
#pragma unroll
        for (int q = 0; q < 8; q++) ((uint4*)dst)[q] = *(uint4*)&hiw[q * 4];
    }
    {
        unsigned char* dst = g_xn + ((size_t)(1 * 64 + b * 8 + (t >> 5)) * 256 + f) * 4096 + (t & 31) * 128;
#pragma unroll
        for (int q = 0; q < 8; q++) ((uint4*)dst)[q] = *(uint4*)&hiw[q * 4];
    }
}

// ---------------- GRU recurrent kernel (mma.sync fp16, cross-step pipelined) ----------------
__global__ void __launch_bounds__(256, 1) gru_kernel() {
    extern __shared__ __align__(16) unsigned char smem[];
    const uint32_t sbase = smem_u32(smem);
    const int g   = blockIdx.x >> 6;
    const int sq  = blockIdx.x & 63;
    const int tid = threadIdx.x;
    const int w   = tid >> 5;
    const int lane = tid & 31;

    // stage W into smem (400B row stride)
    {
        const uint4* src = (const uint4*)(g_wh16 + (size_t)g * 73728);
        for (int i = 0; i < 36; i++) {
            int idx = tid + i * 256;
            int row = idx / 24, u = idx % 24;
            *(uint4*)(smem + row * 400 + u * 16) = src[idx];
        }
    }
    const uint4* xsrc = (const uint4*)(g_xn + ((size_t)(g * 64 + sq) * 256) * 4096);
    // stage x(0), x(1)
    {
        uint4 v0 = xsrc[tid];
        uint4 v1 = xsrc[256 + tid];
        const uint32_t xo = (tid >> 3) * XBUF_STRIDE + (tid & 7) * 16;
        *(uint4*)(smem + XBUF_OFF + xo) = v0;
        *(uint4*)(smem + XBUF_OFF + XBUF_SZ + xo) = v1;
    }
    const int jw = lane >> 2;
    const float bR0 = g_bias[g * 512 + 0 + w * 16 + jw], bR1 = g_bias[g * 512 + 0 + w * 16 + jw + 8];
    const float bZ0 = g_bias[g * 512 + 128 + w * 16 + jw], bZ1 = g_bias[g * 512 + 128 + w * 16 + jw + 8];
    const float bI0 = g_bias[g * 512 + 256 + w * 16 + jw], bI1 = g_bias[g * 512 + 256 + w * 16 + jw + 8];
    const float bH0 = g_bias[g * 512 + 384 + w * 16 + jw], bH1 = g_bias[g * 512 + 384 + w * 16 + jw + 8];
    __syncthreads();

    const uint32_t aRow  = sbase + (uint32_t)(w * 48 + (lane & 15)) * 400 + ((lane >> 4) & 1) * 16;
    const uint32_t bCol  = ((lane >> 3) & 1) * 16;
    const uint32_t xRowB = (uint32_t)(lane & 7) * XBUF_STRIDE + bCol;
    const uint32_t hRowB = (uint32_t)(lane & 7) * HBUF_STRIDE + bCol;
    const uint32_t xStO  = (uint32_t)(tid >> 3) * XBUF_STRIDE + (tid & 7) * 16;

    float hold[16];
#pragma unroll
    for (int i = 0; i < 16; i++) hold[i] = 0.0f;

    float aR[4][4], aZ[4][4], aNI[4][4], aNH[4][4];
#pragma unroll
    for (int nt = 0; nt < 4; nt++) {
        aR[nt][0] = bR0; aR[nt][1] = bR0; aR[nt][2] = bR1; aR[nt][3] = bR1;
        aZ[nt][0] = bZ0; aZ[nt][1] = bZ0; aZ[nt][2] = bZ1; aZ[nt][3] = bZ1;
        aNI[nt][0] = bI0; aNI[nt][1] = bI0; aNI[nt][2] = bI1; aNI[nt][3] = bI1;
        aNH[nt][0] = bH0; aNH[nt][1] = bH0; aNH[nt][2] = bH1; aNH[nt][3] = bH1;
    }
    // x-part mma for step 0
    {
        const uint32_t xb = sbase + XBUF_OFF;
#pragma unroll
        for (int kt = 0; kt < 4; kt++) {
            uint32_t af[3][4];
#pragma unroll
            for (int mt = 0; mt < 3; mt++) ldsm4(af[mt], aRow + mt * 6400 + kt * 32);
#pragma unroll
            for (int nt = 0; nt < 4; nt++) {
                uint32_t bf[2];
                ldsm2(bf, xb + xRowB + nt * (8 * XBUF_STRIDE) + kt * 32);
                mma16816(aR[nt],  af[0], bf);
                mma16816(aZ[nt],  af[1], bf);
                mma16816(aNI[nt], af[2], bf);
            }
        }
    }

    int i1 = 1, i2 = 2;   // (s+1)%3, (s+2)%3
    for (int s = 0; s < 256; s++) {
        uint4 xv;
        if (s < 254) xv = xsrc[(size_t)(s + 2) * 256 + tid];
        const uint32_t hcur = sbase + HBUF_OFF + (s & 1) * HBUF_SZ;
        const uint32_t hnxtOff = HBUF_OFF + ((s & 1) ^ 1) * HBUF_SZ;

        // h-part mma for step s (skipped at s=0: h=0)
        if (s > 0) {
#pragma unroll
            for (int kt = 4; kt < 12; kt++) {
                uint32_t af[3][4];
#pragma unroll
                for (int mt = 0; mt < 3; mt++) ldsm4(af[mt], aRow + mt * 6400 + kt * 32);
                uint32_t bh[4][2];
#pragma unroll
                for (int nt = 0; nt < 4; nt++)
                    ldsm2(bh[nt], hcur + hRowB + nt * (8 * HBUF_STRIDE) + (kt - 4) * 32);
#pragma unroll
                for (int nt = 0; nt < 4; nt++) {
                    mma16816(aR[nt],  af[0], bh[nt]);
                    mma16816(aZ[nt],  af[1], bh[nt]);
                    mma16816(aNH[nt], af[2], bh[nt]);
                }
            }
        }

        // x-part mma for step s+1 into second accumulator set
        float xRa[4][4], xZa[4][4], xNIa[4][4];
        if (s < 255) {
#pragma unroll
            for (int nt = 0; nt < 4; nt++) {
                xRa[nt][0] = bR0; xRa[nt][1] = bR0; xRa[nt][2] = bR1; xRa[nt][3] = bR1;
                xZa[nt][0] = bZ0; xZa[nt][1] = bZ0; xZa[nt][2] = bZ1; xZa[nt][3] = bZ1;
                xNIa[nt][0] = bI0; xNIa[nt][1] = bI0; xNIa[nt][2] = bI1; xNIa[nt][3] = bI1;
            }
            const uint32_t xb = sbase + XBUF_OFF + (uint32_t)i1 * XBUF_SZ;
#pragma unroll
            for (int kt = 0; kt < 4; kt++) {
                uint32_t af[3][4];
#pragma unroll
                for (int mt = 0; mt < 3; mt++) ldsm4(af[mt], aRow + mt * 6400 + kt * 32);
#pragma unroll
                for (int nt = 0; nt < 4; nt++) {
                    uint32_t bf[2];
                    ldsm2(bf, xb + xRowB + nt * (8 * XBUF_STRIDE) + kt * 32);
                    mma16816(xRa[nt],  af[0], bf);
                    mma16816(xZa[nt],  af[1], bf);
                    mma16816(xNIa[nt], af[2], bf);
                }
            }
        }

        // epilogue for step s
#pragma unroll
        for (int nt = 0; nt < 4; nt++) {
#pragma unroll
            for (int q = 0; q < 2; q++) {
                float hv[2];
#pragma unroll
                for (int t2 = 0; t2 < 2; t2++) {
                    const int p = q + t2 * 2;
                    const int idx = nt * 4 + p;
                    float r  = siga(aR[nt][p]);
                    float z  = siga(aZ[nt][p]);
                    float nn = tanha(fmaf(r, aNH[nt][p], aNI[nt][p]));
                    float h  = nn + z * (hold[idx] - nn);
                    hold[idx] = h;
                    hv[t2] = h;
                    if (s == 255) {
                        const int n = nt * 8 + (lane & 3) * 2 + q;
                        const int j = w * 16 + jw + t2 * 8;
                        g_hout[((size_t)g * NSEQ + sq * 32 + n) * 128 + j] = h;
                    }
                }
                if (s < 255) {
                    const int n = nt * 8 + (lane & 3) * 2 + q;
                    const uint32_t hb = hnxtOff + n * HBUF_STRIDE + w * 32 + jw * 4;
                    *(uint32_t*)(smem + hb) = pack_h2(__float2half_rn(hv[0]), __float2half_rn(hv[1]));
                }
            }
        }

        // stage x(s+2)
        if (s < 254)
            *(uint4*)(smem + XBUF_OFF + (uint32_t)i2 * XBUF_SZ + xStO) = xv;
        __syncthreads();

        // roll accumulators
        if (s < 255) {
#pragma unroll
            for (int nt = 0; nt < 4; nt++)
#pragma unroll
                for (int p = 0; p < 4; p++) {
                    aR[nt][p] = xRa[nt][p];
                    aZ[nt][p] = xZa[nt][p];
                    aNI[nt][p] = xNIa[nt][p];
                }
#pragma unroll
            for (int nt = 0; nt < 4; nt++) {
                aNH[nt][0] = bH0; aNH[nt][1] = bH0; aNH[nt][2] = bH1; aNH[nt][3] = bH1;
            }
        }
        i1 = (i1 == 2) ? 0 : i1 + 1;
        i2 = (i2 == 2) ? 0 : i2 + 1;
    }
}

// ---------------- output projection + broadcast ----------------
__global__ void out_kernel(const float* __restrict__ Wp, const float* __restrict__ bp,
                           float* __restrict__ out) {
    __shared__ float s_vec[128];
    __shared__ float part_s[4][64];
    __shared__ float s_out[64];
    const int bt = blockIdx.x;
    const int b  = bt >> 8;
    const int t  = bt & 255;
    const int tid = threadIdx.x;
    const int nidx = b * 256 + t;

    if (tid < 128)
        s_vec[tid] = g_hout[(size_t)nidx * 128 + tid] +
                     g_hout[((size_t)NSEQ + nidx) * 128 + tid];
    __syncthreads();

    const int c = tid & 63, p = tid >> 6;
    float sum = 0.0f;
#pragma unroll
    for (int h = 0; h < 32; h++)
        sum = fmaf(Wp[c * 128 + p * 32 + h], s_vec[p * 32 + h], sum);
    part_s[p][c] = sum;
    __syncthreads();
    if (tid < 64)
        s_out[tid] = bp[tid] + part_s[0][tid] + part_s[1][tid] + part_s[2][tid] + part_s[3][tid];
    __syncthreads();

    float4* o4 = (float4*)out;
    const size_t base4 = ((size_t)b * 64) * 16384 + (size_t)t * 64;
    for (int e = tid; e < 4096; e += 256) {
        int c2 = e >> 6, f4 = e & 63;
        float v = s_out[c2];
        o4[base4 + (size_t)c2 * 16384 + f4] = make_float4(v, v, v, v);
    }
}

// ---------------- launcher ----------------
extern "C" void kernel_launch(void* const* d_in, const int* in_sizes, int n_in,
                              void* d_out, int out_size) {
    const float* x     = (const float*)d_in[0];
    const float* Wih_t = (const float*)d_in[1];
    const float* Whh_t = (const float*)d_in[2];
    const float* bih_t = (const float*)d_in[3];
    const float* bhh_t = (const float*)d_in[4];
    const float* Wih_f = (const float*)d_in[5];
    const float* Whh_f = (const float*)d_in[6];
    const float* bih_f = (const float*)d_in[7];
    const float* bhh_f = (const float*)d_in[8];
    const float* Wp    = (const float*)d_in[9];
    const float* bp    = (const float*)d_in[10];
    float* out = (float*)d_out;

    cudaFuncSetAttribute(gru_kernel, cudaFuncAttributeMaxDynamicSharedMemorySize, GRU_SMEM);
    cudaFuncSetAttribute(transpose_kernel, cudaFuncAttributeMaxDynamicSharedMemorySize, 65792);

    prep_kernel<<<(2 * 384 * 192 + 256 + 255) / 256, 256>>>(Wih_t, Whh_t, bih_t, bhh_t,
                                                            Wih_f, Whh_f, bih_f, bhh_f);
    transpose_kernel<<<8 * 32 * 8, 256, 65792>>>(x);
    gru_kernel<<<128, 256, GRU_SMEM>>>();
    out_kernel<<<2048, 256>>>(Wp, bp, out);
}